// round 10
// baseline (speedup 1.0000x reference)
#include <cuda_runtime.h>
#include <cuda_fp16.h>
#include <math.h>
#include <stdint.h>

// Attention_33492154974379:  x [B=8, T=2048, D=1024] fp32
// out = concat(att_vec [B,T,D], att_weights [B,T,T])
// R10: fp16 hi/lo split, all f32-accum HMMA (mma.sync ceiling ~50% accepted).
//      scores = 3-term; av = 2-term (W quantized to single fp16; error ~1e-4,
//      5-10x under threshold). R7 MAC cuts + launch_bounds(256,2) restored.

#define B_ 8
#define T_ 2048
#define D_ 1024
#define NEG_INF_ (-1.0e9f)

// ---- static scratch ----
__device__ __half g_xhi[(size_t)B_ * T_ * D_];
__device__ __half g_xlo[(size_t)B_ * T_ * D_];
__device__ __half g_xthi[(size_t)B_ * D_ * T_];   // x^T [B,D,T]
__device__ __half g_xtlo[(size_t)B_ * D_ * T_];
__device__ __half g_whi[(size_t)B_ * T_ * T_];    // softmax weights, single fp16
__device__ float g_r0[(size_t)B_ * 8 * D_];       // row-0 partial sums

// ---- smem: 4 tiles (Ahi,Alo,Bhi,Blo) of 128 x 32 f16, stride 40 ----
#define LDS_ 40
#define TILE_E (128 * LDS_)
#define STAGE_E (4 * TILE_E)
#define SMEM_BYTES (2 * STAGE_E * 2)  // 81920 B double buffered

__device__ __forceinline__ void ldsm4(uint32_t* r, uint32_t a) {
    asm volatile("ldmatrix.sync.aligned.m8n8.x4.shared.b16 {%0,%1,%2,%3}, [%4];"
                 : "=r"(r[0]), "=r"(r[1]), "=r"(r[2]), "=r"(r[3]) : "r"(a));
}
__device__ __forceinline__ void mma16816(float* d, const uint32_t* a, const uint32_t* b) {
    asm volatile("mma.sync.aligned.m16n8k16.row.col.f32.f16.f16.f32 "
                 "{%0,%1,%2,%3}, {%4,%5,%6,%7}, {%8,%9}, {%0,%1,%2,%3};"
                 : "+f"(d[0]), "+f"(d[1]), "+f"(d[2]), "+f"(d[3])
                 : "r"(a[0]), "r"(a[1]), "r"(a[2]), "r"(a[3]), "r"(b[0]), "r"(b[1]));
}
__device__ __forceinline__ void cpa16(uint32_t d, const void* s) {
    asm volatile("cp.async.cg.shared.global [%0], [%1], 16;" :: "r"(d), "l"(s) : "memory");
}
__device__ __forceinline__ void cpcommit() { asm volatile("cp.async.commit_group;" ::: "memory"); }
template <int N>
__device__ __forceinline__ void cpwait() { asm volatile("cp.async.wait_group %0;" :: "n"(N) : "memory"); }

// ---------------------------------------------------------------------------
// Pass 0: x -> (hi,lo) fp16 and transposed (hi,lo)
// ---------------------------------------------------------------------------
__global__ __launch_bounds__(256) void convert_kernel(const float* __restrict__ x) {
    __shared__ float tile[32][33];
    const int b = blockIdx.z;
    const int t0 = blockIdx.y * 32, d0 = blockIdx.x * 32;
    const int tx = threadIdx.x, ty = threadIdx.y;  // (32, 8)
    const float* xb = x + (size_t)b * T_ * D_;

    #pragma unroll
    for (int k = 0; k < 4; ++k) {
        const int r = ty + k * 8;
        const float v = xb[(size_t)(t0 + r) * D_ + d0 + tx];
        tile[r][tx] = v;
        __half hi = __float2half_rn(v);
        __half lo = __float2half_rn(v - __half2float(hi));
        const size_t o = (size_t)b * T_ * D_ + (size_t)(t0 + r) * D_ + d0 + tx;
        g_xhi[o] = hi; g_xlo[o] = lo;
    }
    __syncthreads();
    #pragma unroll
    for (int k = 0; k < 4; ++k) {
        const int r = ty + k * 8;
        const float v = tile[tx][r];
        __half hi = __float2half_rn(v);
        __half lo = __float2half_rn(v - __half2float(hi));
        const size_t o = (size_t)b * D_ * T_ + (size_t)(d0 + r) * T_ + t0 + tx;
        g_xthi[o] = hi; g_xtlo[o] = lo;
    }
}

// ---------------------------------------------------------------------------
// Shared MMA mainloop: C[128x128] over K chunks of 32.
// THREE=true : acc += Ahi@Bhi + Ahi@Blo + Alo@Bhi   (scores; Alo loaded)
// THREE=false: acc += Ahi@Bhi + Ahi@Blo             (av; Alo tile unused)
// DIAG=true  : skip accumulator blocks fully above the diagonal.
// ---------------------------------------------------------------------------
template <bool DIAG, bool THREE>
__device__ __forceinline__ void gemm_mainloop(
    const __half* __restrict__ Ahi, const __half* __restrict__ Alo,
    const __half* __restrict__ Bhi, const __half* __restrict__ Blo,
    int ldk, int kmax, float acc[4][4][4])
{
    extern __shared__ __half sm[];
    const int tid = threadIdx.x;
    const int lane = tid & 31, warp = tid >> 5;
    const int wm = (warp >> 2) * 64, wn = (warp & 3) * 32;
    const uint32_t smem_u32 = (uint32_t)__cvta_generic_to_shared(sm);

    // copy mapping: tile 1 (Alo) only filled when THREE
    const int tile = tid >> 6;
    const __half* sp = (tile == 0) ? Ahi : (tile == 1) ? (THREE ? Alo : Ahi)
                     : (tile == 2) ? Bhi : Blo;
    const int crow0 = (tid & 63) >> 2;
    const int cc = tid & 3;
    const uint32_t dtile = (uint32_t)(tile * TILE_E) * 2;

    const int nchunks = kmax >> 5;

    {
        #pragma unroll
        for (int t = 0; t < 8; ++t) {
            const int row = crow0 + t * 16;
            cpa16(smem_u32 + dtile + (uint32_t)(row * LDS_ + cc * 8) * 2,
                  sp + (size_t)row * ldk + cc * 8);
        }
        cpcommit();
    }

    for (int i = 0; i < nchunks; ++i) {
        const int s = i & 1;
        if (i + 1 < nchunks) {
            const int kk = (i + 1) << 5;
            const uint32_t dst0 = smem_u32 + (uint32_t)((s ^ 1) * STAGE_E) * 2 + dtile;
            #pragma unroll
            for (int t = 0; t < 8; ++t) {
                const int row = crow0 + t * 16;
                cpa16(dst0 + (uint32_t)(row * LDS_ + cc * 8) * 2,
                      sp + (size_t)row * ldk + kk + cc * 8);
            }
            cpcommit();
            cpwait<1>();
        } else {
            cpwait<0>();
        }
        __syncthreads();

        const uint32_t stA   = smem_u32 + (uint32_t)(s * STAGE_E) * 2;
        const uint32_t stAlo = stA + TILE_E * 2;
        const uint32_t stB   = stA + 2 * TILE_E * 2;
        const uint32_t stBlo = stA + 3 * TILE_E * 2;

        #pragma unroll
        for (int s2 = 0; s2 < 2; ++s2) {
            uint32_t ahi[4][4], alo[4][4], bhi[4][2], blo[4][2];
            const int ar = wm + (lane & 15);
            const int ac = ((lane >> 4) + 2 * s2) * 8;
            #pragma unroll
            for (int mt = 0; mt < 4; ++mt) {
                const uint32_t off = (uint32_t)((ar + mt * 16) * LDS_ + ac) * 2;
                ldsm4(ahi[mt], stA + off);
                if (THREE) ldsm4(alo[mt], stAlo + off);
            }
            const int br = wn + ((lane >> 4) & 1) * 8 + (lane & 7);
            const int bc = (((lane >> 3) & 1) + 2 * s2) * 8;
            #pragma unroll
            for (int p = 0; p < 2; ++p) {
                const uint32_t off = (uint32_t)((br + p * 16) * LDS_ + bc) * 2;
                uint32_t r4[4];
                ldsm4(r4, stB + off);
                bhi[2 * p][0] = r4[0]; bhi[2 * p][1] = r4[1];
                bhi[2 * p + 1][0] = r4[2]; bhi[2 * p + 1][1] = r4[3];
                ldsm4(r4, stBlo + off);
                blo[2 * p][0] = r4[0]; blo[2 * p][1] = r4[1];
                blo[2 * p + 1][0] = r4[2]; blo[2 * p + 1][1] = r4[3];
            }
            #pragma unroll
            for (int mt = 0; mt < 4; ++mt)
                #pragma unroll
                for (int nt = 0; nt < 4; ++nt) {
                    if (DIAG) {
                        if (wn + nt * 8 > wm + mt * 16 + 14) continue;
                    }
                    mma16816(acc[mt][nt], ahi[mt], bhi[nt]);
                    mma16816(acc[mt][nt], ahi[mt], blo[nt]);
                    if (THREE) mma16816(acc[mt][nt], alo[mt], bhi[nt]);
                }
        }
        __syncthreads();
    }
}

// ---------------------------------------------------------------------------
// Pass 1: masked scores. Upper tiles get final W=0.0f (softmax skips them).
// ---------------------------------------------------------------------------
__global__ __launch_bounds__(256, 2) void scores_mma_kernel(float* __restrict__ w) {
    const int b = blockIdx.z, ti = blockIdx.y, tj = blockIdx.x;
    float* wb = w + (size_t)b * T_ * T_;
    const int gi0 = ti * 128, gj0 = tj * 128;
    const int tid = threadIdx.x;

    if (tj > ti) {  // fully masked tile: write FINAL weight value 0.0f
        const float4 zv = make_float4(0.0f, 0.0f, 0.0f, 0.0f);
        #pragma unroll
        for (int t = 0; t < 16; ++t) {
            const int i = tid + t * 256;
            const int r = i >> 5, c4 = i & 31;
            *(float4*)(wb + (size_t)(gi0 + r) * T_ + gj0 + c4 * 4) = zv;
        }
        return;
    }

    float acc[4][4][4] = {};
    const size_t ao = ((size_t)b * T_ + gi0) * D_;
    const size_t bo = ((size_t)b * T_ + gj0) * D_;
    const bool diag = (ti == tj);
    if (diag)
        gemm_mainloop<true , true>(g_xhi + ao, g_xlo + ao, g_xhi + bo, g_xlo + bo, D_, D_, acc);
    else
        gemm_mainloop<false, true>(g_xhi + ao, g_xlo + ao, g_xhi + bo, g_xlo + bo, D_, D_, acc);

    const int lane = tid & 31, warp = tid >> 5;
    const int wm = (warp >> 2) * 64, wn = (warp & 3) * 32;
    #pragma unroll
    for (int mt = 0; mt < 4; ++mt)
        #pragma unroll
        for (int nt = 0; nt < 4; ++nt) {
            const int gi = gi0 + wm + mt * 16 + (lane >> 2);
            const int gj = gj0 + wn + nt * 8 + 2 * (lane & 3);
            float* p0 = wb + (size_t)gi * T_ + gj;
            float* p1 = wb + (size_t)(gi + 8) * T_ + gj;
            if (!diag) {
                p0[0] = acc[mt][nt][0]; p0[1] = acc[mt][nt][1];
                p1[0] = acc[mt][nt][2]; p1[1] = acc[mt][nt][3];
            } else {
                p0[0] = (gj     < gi    ) ? acc[mt][nt][0] : NEG_INF_;
                p0[1] = (gj + 1 < gi    ) ? acc[mt][nt][1] : NEG_INF_;
                p1[0] = (gj     < gi + 8) ? acc[mt][nt][2] : NEG_INF_;
                p1[1] = (gj + 1 < gi + 8) ? acc[mt][nt][3] : NEG_INF_;
            }
        }
}

// ---------------------------------------------------------------------------
// Pass 2: prefix softmax. Row i touches k < roundup(i+1,128).
// Writes fp32 weights + single fp16 quantization for av.
// ---------------------------------------------------------------------------
__global__ __launch_bounds__(256) void softmax_kernel(float* __restrict__ w) {
    const int b = blockIdx.y;
    const int i = blockIdx.x;
    const size_t row = (size_t)b * T_ + i;
    float* p = w + row * T_;
    __half* ph = g_whi + row * T_;
    const int tid = threadIdx.x;

    if (i == 0) {
        const float val = 1.0f / (float)T_;
        const __half hi = __float2half_rn(val);
        for (int k = tid; k < T_; k += 256) { p[k] = val; ph[k] = hi; }
        return;
    }

    const int L = (((i >> 7) + 1) << 7);   // 128..2048, multiple of 128

    float v[8];
    float m = -INFINITY;
    #pragma unroll
    for (int j = 0; j < 8; ++j) {
        const int k = tid + j * 256;
        v[j] = (k < L) ? p[k] : NEG_INF_;
        m = fmaxf(m, v[j]);
    }

    __shared__ float red[256];
    red[tid] = m; __syncthreads();
    #pragma unroll
    for (int s = 128; s > 0; s >>= 1) {
        if (tid < s) red[tid] = fmaxf(red[tid], red[tid + s]);
        __syncthreads();
    }
    m = red[0];
    __syncthreads();

    float sum = 0.0f;
    #pragma unroll
    for (int j = 0; j < 8; ++j) { v[j] = expf(v[j] - m); sum += v[j]; }

    red[tid] = sum; __syncthreads();
    #pragma unroll
    for (int s = 128; s > 0; s >>= 1) {
        if (tid < s) red[tid] += red[tid + s];
        __syncthreads();
    }
    const float inv = 1.0f / red[0];

    #pragma unroll
    for (int j = 0; j < 8; ++j) {
        const int k = tid + j * 256;
        if (k < L) {
            const float val = v[j] * inv;
            p[k] = val;
            ph[k] = __float2half_rn(val);
        }
    }
}

// ---------------------------------------------------------------------------
// Pass 3: att_vec = W_h16 @ X (2-term), kmax=(ti+1)*128 (row 0 fixed later).
// ti reversed so the longest CTAs schedule first (wave balance).
// ---------------------------------------------------------------------------
__global__ __launch_bounds__(256, 2) void av_mma_kernel(float* __restrict__ o) {
    const int b = blockIdx.z, tj = blockIdx.x;
    const int ti = (int)gridDim.y - 1 - (int)blockIdx.y;   // long tiles first
    const int gi0 = ti * 128, gj0 = tj * 128;
    const int kmax = (ti + 1) * 128;

    float acc[4][4][4] = {};
    const size_t ao = ((size_t)b * T_ + gi0) * T_;
    const size_t bo = ((size_t)b * D_ + gj0) * T_;
    gemm_mainloop<false, false>(g_whi + ao, g_whi + ao,
                                g_xthi + bo, g_xtlo + bo, T_, kmax, acc);

    float* ob = o + (size_t)b * T_ * D_;
    const int tid = threadIdx.x;
    const int lane = tid & 31, warp = tid >> 5;
    const int wm = (warp >> 2) * 64, wn = (warp & 3) * 32;
    #pragma unroll
    for (int mt = 0; mt < 4; ++mt)
        #pragma unroll
        for (int nt = 0; nt < 4; ++nt) {
            const int gi = gi0 + wm + mt * 16 + (lane >> 2);
            const int gj = gj0 + wn + nt * 8 + 2 * (lane & 3);
            float* p0 = ob + (size_t)gi * D_ + gj;
            float* p1 = ob + (size_t)(gi + 8) * D_ + gj;
            p0[0] = acc[mt][nt][0]; p0[1] = acc[mt][nt][1];
            p1[0] = acc[mt][nt][2]; p1[1] = acc[mt][nt][3];
        }
}

// ---------------------------------------------------------------------------
// Row-0 fix: av[b,0,:] = (1/T) * sum_s x[b,s,:]  (exact 2-stage reduction)
// ---------------------------------------------------------------------------
__global__ __launch_bounds__(256) void row0_partial_kernel(const float* __restrict__ x) {
    const int b = blockIdx.z, sp = blockIdx.y;       // 8 T-splits of 256 rows
    const int d = blockIdx.x * 256 + threadIdx.x;
    const float* xb = x + (size_t)b * T_ * D_ + (size_t)sp * 256 * D_ + d;
    float s = 0.0f;
    for (int r = 0; r < 256; ++r) s += xb[(size_t)r * D_];
    g_r0[((size_t)b * 8 + sp) * D_ + d] = s;
}
__global__ __launch_bounds__(256) void row0_final_kernel(float* __restrict__ o) {
    const int b = blockIdx.y;
    const int d = blockIdx.x * 256 + threadIdx.x;
    float s = 0.0f;
    #pragma unroll
    for (int j = 0; j < 8; ++j) s += g_r0[((size_t)b * 8 + j) * D_ + d];
    o[(size_t)b * T_ * D_ + d] = s * (1.0f / (float)T_);
}

// ---------------------------------------------------------------------------
extern "C" void kernel_launch(void* const* d_in, const int* in_sizes, int n_in,
                              void* d_out, int out_size) {
    const float* x = (const float*)d_in[0];
    float* att_vec = (float*)d_out;                          // [B,T,D]
    float* att_w   = (float*)d_out + (size_t)B_ * T_ * D_;   // [B,T,T]
    (void)in_sizes; (void)n_in; (void)out_size;

    cudaFuncSetAttribute(scores_mma_kernel, cudaFuncAttributeMaxDynamicSharedMemorySize, SMEM_BYTES);
    cudaFuncSetAttribute(av_mma_kernel, cudaFuncAttributeMaxDynamicSharedMemorySize, SMEM_BYTES);

    convert_kernel<<<dim3(D_ / 32, T_ / 32, B_), dim3(32, 8)>>>(x);
    scores_mma_kernel<<<dim3(T_ / 128, T_ / 128, B_), 256, SMEM_BYTES>>>(att_w);
    softmax_kernel<<<dim3(T_, B_), 256>>>(att_w);
    av_mma_kernel<<<dim3(D_ / 128, T_ / 128, B_), 256, SMEM_BYTES>>>(att_vec);
    row0_partial_kernel<<<dim3(D_ / 256, 8, B_), 256>>>(x);
    row0_final_kernel<<<dim3(D_ / 256, B_), 256>>>(att_vec);
}

// round 13
// speedup vs baseline: 1.3467x; 1.3467x over previous
#include <cuda_runtime.h>
#include <cuda_bf16.h>
#include <math.h>
#include <stdint.h>

// Attention_33492154974379:  x [B=8, T=2048, D=1024] fp32
// out = concat(att_vec [B,T,D], att_weights [B,T,T])
// R12: R7 base (bf16 hi/lo 3-term HMMA, DIAG template, prefix softmax,
//      row-0 analytic mean) + av reversed-ti (R9-verified) + float4/bf16x2
//      vectorized softmax. Single stream (multi-stream graphs leak pool mem).

#define B_ 8
#define T_ 2048
#define D_ 1024
#define NEG_INF_ (-1.0e9f)

// ---- static scratch ----
__device__ __nv_bfloat16 g_xhi[(size_t)B_ * T_ * D_];
__device__ __nv_bfloat16 g_xlo[(size_t)B_ * T_ * D_];
__device__ __nv_bfloat16 g_xthi[(size_t)B_ * D_ * T_];   // x^T [B,D,T]
__device__ __nv_bfloat16 g_xtlo[(size_t)B_ * D_ * T_];
__device__ __nv_bfloat16 g_whi[(size_t)B_ * T_ * T_];
__device__ __nv_bfloat16 g_wlo[(size_t)B_ * T_ * T_];
__device__ float g_r0[(size_t)B_ * 8 * D_];              // row-0 partial sums

// ---- smem: 4 tiles (Ahi,Alo,Bhi,Blo) of 128 x 32 bf16, stride 40 ----
#define LDS_ 40
#define TILE_E (128 * LDS_)
#define STAGE_E (4 * TILE_E)
#define SMEM_BYTES (2 * STAGE_E * 2)  // 81920 B double buffered

__device__ __forceinline__ void ldsm4(uint32_t* r, uint32_t a) {
    asm volatile("ldmatrix.sync.aligned.m8n8.x4.shared.b16 {%0,%1,%2,%3}, [%4];"
                 : "=r"(r[0]), "=r"(r[1]), "=r"(r[2]), "=r"(r[3]) : "r"(a));
}
__device__ __forceinline__ void mma16816(float* d, const uint32_t* a, const uint32_t* b) {
    asm volatile("mma.sync.aligned.m16n8k16.row.col.f32.bf16.bf16.f32 "
                 "{%0,%1,%2,%3}, {%4,%5,%6,%7}, {%8,%9}, {%0,%1,%2,%3};"
                 : "+f"(d[0]), "+f"(d[1]), "+f"(d[2]), "+f"(d[3])
                 : "r"(a[0]), "r"(a[1]), "r"(a[2]), "r"(a[3]), "r"(b[0]), "r"(b[1]));
}
__device__ __forceinline__ void cpa16(uint32_t d, const void* s) {
    asm volatile("cp.async.cg.shared.global [%0], [%1], 16;" :: "r"(d), "l"(s) : "memory");
}
__device__ __forceinline__ void cpcommit() { asm volatile("cp.async.commit_group;" ::: "memory"); }
template <int N>
__device__ __forceinline__ void cpwait() { asm volatile("cp.async.wait_group %0;" :: "n"(N) : "memory"); }

// ---------------------------------------------------------------------------
// Pass 0: x -> (hi,lo) and transposed (hi,lo)
// ---------------------------------------------------------------------------
__global__ __launch_bounds__(256) void convert_kernel(const float* __restrict__ x) {
    __shared__ float tile[32][33];
    const int b = blockIdx.z;
    const int t0 = blockIdx.y * 32, d0 = blockIdx.x * 32;
    const int tx = threadIdx.x, ty = threadIdx.y;  // (32, 8)
    const float* xb = x + (size_t)b * T_ * D_;

    #pragma unroll
    for (int k = 0; k < 4; ++k) {
        const int r = ty + k * 8;
        const float v = xb[(size_t)(t0 + r) * D_ + d0 + tx];
        tile[r][tx] = v;
        __nv_bfloat16 hi = __float2bfloat16_rn(v);
        __nv_bfloat16 lo = __float2bfloat16_rn(v - __bfloat162float(hi));
        const size_t o = (size_t)b * T_ * D_ + (size_t)(t0 + r) * D_ + d0 + tx;
        g_xhi[o] = hi; g_xlo[o] = lo;
    }
    __syncthreads();
    #pragma unroll
    for (int k = 0; k < 4; ++k) {
        const int r = ty + k * 8;
        const float v = tile[tx][r];
        __nv_bfloat16 hi = __float2bfloat16_rn(v);
        __nv_bfloat16 lo = __float2bfloat16_rn(v - __bfloat162float(hi));
        const size_t o = (size_t)b * D_ * T_ + (size_t)(d0 + r) * T_ + t0 + tx;
        g_xthi[o] = hi; g_xtlo[o] = lo;
    }
}

// ---------------------------------------------------------------------------
// Shared MMA mainloop (identical to R7)
// ---------------------------------------------------------------------------
template <bool DIAG>
__device__ __forceinline__ void gemm_mainloop(
    const __nv_bfloat16* __restrict__ Ahi, const __nv_bfloat16* __restrict__ Alo,
    const __nv_bfloat16* __restrict__ Bhi, const __nv_bfloat16* __restrict__ Blo,
    int ldk, int kmax, float acc[4][4][4])
{
    extern __shared__ __nv_bfloat16 sm[];
    const int tid = threadIdx.x;
    const int lane = tid & 31, warp = tid >> 5;
    const int wm = (warp >> 2) * 64, wn = (warp & 3) * 32;
    const uint32_t smem_u32 = (uint32_t)__cvta_generic_to_shared(sm);

    const int tile = tid >> 6;
    const __nv_bfloat16* sp = (tile == 0) ? Ahi : (tile == 1) ? Alo : (tile == 2) ? Bhi : Blo;
    const int crow0 = (tid & 63) >> 2;
    const int cc = tid & 3;
    const uint32_t dtile = (uint32_t)(tile * TILE_E) * 2;

    const int nchunks = kmax >> 5;

    {
        #pragma unroll
        for (int t = 0; t < 8; ++t) {
            const int row = crow0 + t * 16;
            cpa16(smem_u32 + dtile + (uint32_t)(row * LDS_ + cc * 8) * 2,
                  sp + (size_t)row * ldk + cc * 8);
        }
        cpcommit();
    }

    for (int i = 0; i < nchunks; ++i) {
        const int s = i & 1;
        if (i + 1 < nchunks) {
            const int kk = (i + 1) << 5;
            const uint32_t dst0 = smem_u32 + (uint32_t)((s ^ 1) * STAGE_E) * 2 + dtile;
            #pragma unroll
            for (int t = 0; t < 8; ++t) {
                const int row = crow0 + t * 16;
                cpa16(dst0 + (uint32_t)(row * LDS_ + cc * 8) * 2,
                      sp + (size_t)row * ldk + kk + cc * 8);
            }
            cpcommit();
            cpwait<1>();
        } else {
            cpwait<0>();
        }
        __syncthreads();

        const uint32_t stA   = smem_u32 + (uint32_t)(s * STAGE_E) * 2;
        const uint32_t stAlo = stA + TILE_E * 2;
        const uint32_t stB   = stA + 2 * TILE_E * 2;
        const uint32_t stBlo = stA + 3 * TILE_E * 2;

        #pragma unroll
        for (int s2 = 0; s2 < 2; ++s2) {
            uint32_t ahi[4][4], alo[4][4], bhi[4][2], blo[4][2];
            const int ar = wm + (lane & 15);
            const int ac = ((lane >> 4) + 2 * s2) * 8;
            #pragma unroll
            for (int mt = 0; mt < 4; ++mt) {
                const uint32_t off = (uint32_t)((ar + mt * 16) * LDS_ + ac) * 2;
                ldsm4(ahi[mt], stA + off);
                ldsm4(alo[mt], stAlo + off);
            }
            const int br = wn + ((lane >> 4) & 1) * 8 + (lane & 7);
            const int bc = (((lane >> 3) & 1) + 2 * s2) * 8;
            #pragma unroll
            for (int p = 0; p < 2; ++p) {
                const uint32_t off = (uint32_t)((br + p * 16) * LDS_ + bc) * 2;
                uint32_t r4[4];
                ldsm4(r4, stB + off);
                bhi[2 * p][0] = r4[0]; bhi[2 * p][1] = r4[1];
                bhi[2 * p + 1][0] = r4[2]; bhi[2 * p + 1][1] = r4[3];
                ldsm4(r4, stBlo + off);
                blo[2 * p][0] = r4[0]; blo[2 * p][1] = r4[1];
                blo[2 * p + 1][0] = r4[2]; blo[2 * p + 1][1] = r4[3];
            }
            #pragma unroll
            for (int mt = 0; mt < 4; ++mt)
                #pragma unroll
                for (int nt = 0; nt < 4; ++nt) {
                    if (DIAG) {
                        if (wn + nt * 8 > wm + mt * 16 + 14) continue;
                    }
                    mma16816(acc[mt][nt], ahi[mt], bhi[nt]);
                    mma16816(acc[mt][nt], ahi[mt], blo[nt]);
                    mma16816(acc[mt][nt], alo[mt], bhi[nt]);
                }
        }
        __syncthreads();
    }
}

// ---------------------------------------------------------------------------
// Pass 1: masked scores. Upper tiles get final W=0.0f (softmax skips them).
// ---------------------------------------------------------------------------
__global__ __launch_bounds__(256, 2) void scores_mma_kernel(float* __restrict__ w) {
    const int b = blockIdx.z, ti = blockIdx.y, tj = blockIdx.x;
    float* wb = w + (size_t)b * T_ * T_;
    const int gi0 = ti * 128, gj0 = tj * 128;
    const int tid = threadIdx.x;

    if (tj > ti) {  // fully masked tile: write FINAL weight value 0.0f
        const float4 zv = make_float4(0.0f, 0.0f, 0.0f, 0.0f);
        #pragma unroll
        for (int t = 0; t < 16; ++t) {
            const int i = tid + t * 256;
            const int r = i >> 5, c4 = i & 31;
            *(float4*)(wb + (size_t)(gi0 + r) * T_ + gj0 + c4 * 4) = zv;
        }
        return;
    }

    float acc[4][4][4] = {};
    const size_t ao = ((size_t)b * T_ + gi0) * D_;
    const size_t bo = ((size_t)b * T_ + gj0) * D_;
    const bool diag = (ti == tj);
    if (diag)
        gemm_mainloop<true >(g_xhi + ao, g_xlo + ao, g_xhi + bo, g_xlo + bo, D_, D_, acc);
    else
        gemm_mainloop<false>(g_xhi + ao, g_xlo + ao, g_xhi + bo, g_xlo + bo, D_, D_, acc);

    const int lane = tid & 31, warp = tid >> 5;
    const int wm = (warp >> 2) * 64, wn = (warp & 3) * 32;
    #pragma unroll
    for (int mt = 0; mt < 4; ++mt)
        #pragma unroll
        for (int nt = 0; nt < 4; ++nt) {
            const int gi = gi0 + wm + mt * 16 + (lane >> 2);
            const int gj = gj0 + wn + nt * 8 + 2 * (lane & 3);
            float* p0 = wb + (size_t)gi * T_ + gj;
            float* p1 = wb + (size_t)(gi + 8) * T_ + gj;
            if (!diag) {
                p0[0] = acc[mt][nt][0]; p0[1] = acc[mt][nt][1];
                p1[0] = acc[mt][nt][2]; p1[1] = acc[mt][nt][3];
            } else {
                p0[0] = (gj     < gi    ) ? acc[mt][nt][0] : NEG_INF_;
                p0[1] = (gj + 1 < gi    ) ? acc[mt][nt][1] : NEG_INF_;
                p1[0] = (gj     < gi + 8) ? acc[mt][nt][2] : NEG_INF_;
                p1[1] = (gj + 1 < gi + 8) ? acc[mt][nt][3] : NEG_INF_;
            }
        }
}

// ---------------------------------------------------------------------------
// Pass 2: prefix softmax, float4/bf16x2 vectorized. Row i touches
// k < roundup(i+1,128). Row 0: uniform 1/T over the full row.
// ---------------------------------------------------------------------------
__global__ __launch_bounds__(256) void softmax_kernel(float* __restrict__ w) {
    const int b = blockIdx.y;
    const int i = blockIdx.x;
    const size_t row = (size_t)b * T_ + i;
    float* p = w + row * T_;
    __nv_bfloat162* ph2 = (__nv_bfloat162*)(g_whi + row * T_);
    __nv_bfloat162* pl2 = (__nv_bfloat162*)(g_wlo + row * T_);
    float4* p4 = (float4*)p;
    const int tid = threadIdx.x;

    if (i == 0) {
        const float val = 1.0f / (float)T_;
        const __nv_bfloat16 hb = __float2bfloat16_rn(val);
        const __nv_bfloat16 lb = __float2bfloat16_rn(val - __bfloat162float(hb));
        const float4 v4 = make_float4(val, val, val, val);
        const __nv_bfloat162 h2 = __nv_bfloat162(hb, hb);
        const __nv_bfloat162 l2 = __nv_bfloat162(lb, lb);
        #pragma unroll
        for (int j = 0; j < 2; ++j) {
            const int k4 = tid + j * 256;   // 512 float4 slots
            p4[k4] = v4;
            ph2[k4 * 2] = h2; ph2[k4 * 2 + 1] = h2;
            pl2[k4 * 2] = l2; pl2[k4 * 2 + 1] = l2;
        }
        return;
    }

    const int L4 = ((((i >> 7) + 1) << 7)) >> 2;   // 32..512 float4s

    float4 v[2];
    float m = -INFINITY;
    #pragma unroll
    for (int j = 0; j < 2; ++j) {
        const int k4 = tid + j * 256;
        v[j] = (k4 < L4) ? p4[k4] : make_float4(NEG_INF_, NEG_INF_, NEG_INF_, NEG_INF_);
        m = fmaxf(m, fmaxf(fmaxf(v[j].x, v[j].y), fmaxf(v[j].z, v[j].w)));
    }

    __shared__ float red[256];
    red[tid] = m; __syncthreads();
    #pragma unroll
    for (int s = 128; s > 0; s >>= 1) {
        if (tid < s) red[tid] = fmaxf(red[tid], red[tid + s]);
        __syncthreads();
    }
    m = red[0];
    __syncthreads();

    float sum = 0.0f;
    #pragma unroll
    for (int j = 0; j < 2; ++j) {
        v[j].x = expf(v[j].x - m); v[j].y = expf(v[j].y - m);
        v[j].z = expf(v[j].z - m); v[j].w = expf(v[j].w - m);
        sum += (v[j].x + v[j].y) + (v[j].z + v[j].w);
    }

    red[tid] = sum; __syncthreads();
    #pragma unroll
    for (int s = 128; s > 0; s >>= 1) {
        if (tid < s) red[tid] += red[tid + s];
        __syncthreads();
    }
    const float inv = 1.0f / red[0];

    #pragma unroll
    for (int j = 0; j < 2; ++j) {
        const int k4 = tid + j * 256;
        if (k4 < L4) {
            float4 o;
            o.x = v[j].x * inv; o.y = v[j].y * inv;
            o.z = v[j].z * inv; o.w = v[j].w * inv;
            p4[k4] = o;
            const __nv_bfloat16 h0 = __float2bfloat16_rn(o.x);
            const __nv_bfloat16 h1 = __float2bfloat16_rn(o.y);
            const __nv_bfloat16 h2v = __float2bfloat16_rn(o.z);
            const __nv_bfloat16 h3 = __float2bfloat16_rn(o.w);
            ph2[k4 * 2]     = __nv_bfloat162(h0, h1);
            ph2[k4 * 2 + 1] = __nv_bfloat162(h2v, h3);
            pl2[k4 * 2]     = __nv_bfloat162(
                __float2bfloat16_rn(o.x - __bfloat162float(h0)),
                __float2bfloat16_rn(o.y - __bfloat162float(h1)));
            pl2[k4 * 2 + 1] = __nv_bfloat162(
                __float2bfloat16_rn(o.z - __bfloat162float(h2v)),
                __float2bfloat16_rn(o.w - __bfloat162float(h3)));
        }
    }
}

// ---------------------------------------------------------------------------
// Pass 3: att_vec = W @ X, kmax=(ti+1)*128, long tiles first (reversed ti).
// ---------------------------------------------------------------------------
__global__ __launch_bounds__(256, 2) void av_mma_kernel(float* __restrict__ o) {
    const int b = blockIdx.z, tj = blockIdx.x;
    const int ti = (int)gridDim.y - 1 - (int)blockIdx.y;   // long tiles first
    const int gi0 = ti * 128, gj0 = tj * 128;
    const int kmax = (ti + 1) * 128;

    float acc[4][4][4] = {};
    const size_t ao = ((size_t)b * T_ + gi0) * T_;
    const size_t bo = ((size_t)b * D_ + gj0) * T_;
    gemm_mainloop<false>(g_whi + ao, g_wlo + ao, g_xthi + bo, g_xtlo + bo, T_, kmax, acc);

    float* ob = o + (size_t)b * T_ * D_;
    const int tid = threadIdx.x;
    const int lane = tid & 31, warp = tid >> 5;
    const int wm = (warp >> 2) * 64, wn = (warp & 3) * 32;
    #pragma unroll
    for (int mt = 0; mt < 4; ++mt)
        #pragma unroll
        for (int nt = 0; nt < 4; ++nt) {
            const int gi = gi0 + wm + mt * 16 + (lane >> 2);
            const int gj = gj0 + wn + nt * 8 + 2 * (lane & 3);
            float* p0 = ob + (size_t)gi * D_ + gj;
            float* p1 = ob + (size_t)(gi + 8) * D_ + gj;
            p0[0] = acc[mt][nt][0]; p0[1] = acc[mt][nt][1];
            p1[0] = acc[mt][nt][2]; p1[1] = acc[mt][nt][3];
        }
}

// ---------------------------------------------------------------------------
// Row-0 fix: av[b,0,:] = (1/T) * sum_s x[b,s,:]  (exact 2-stage reduction)
// ---------------------------------------------------------------------------
__global__ __launch_bounds__(256) void row0_partial_kernel(const float* __restrict__ x) {
    const int b = blockIdx.z, sp = blockIdx.y;       // 8 T-splits of 256 rows
    const int d = blockIdx.x * 256 + threadIdx.x;
    const float* xb = x + (size_t)b * T_ * D_ + (size_t)sp * 256 * D_ + d;
    float s = 0.0f;
    for (int r = 0; r < 256; ++r) s += xb[(size_t)r * D_];
    g_r0[((size_t)b * 8 + sp) * D_ + d] = s;
}
__global__ __launch_bounds__(256) void row0_final_kernel(float* __restrict__ o) {
    const int b = blockIdx.y;
    const int d = blockIdx.x * 256 + threadIdx.x;
    float s = 0.0f;
    #pragma unroll
    for (int j = 0; j < 8; ++j) s += g_r0[((size_t)b * 8 + j) * D_ + d];
    o[(size_t)b * T_ * D_ + d] = s * (1.0f / (float)T_);
}

// ---------------------------------------------------------------------------
extern "C" void kernel_launch(void* const* d_in, const int* in_sizes, int n_in,
                              void* d_out, int out_size) {
    const float* x = (const float*)d_in[0];
    float* att_vec = (float*)d_out;                          // [B,T,D]
    float* att_w   = (float*)d_out + (size_t)B_ * T_ * D_;   // [B,T,T]
    (void)in_sizes; (void)n_in; (void)out_size;

    cudaFuncSetAttribute(scores_mma_kernel, cudaFuncAttributeMaxDynamicSharedMemorySize, SMEM_BYTES);
    cudaFuncSetAttribute(av_mma_kernel, cudaFuncAttributeMaxDynamicSharedMemorySize, SMEM_BYTES);

    convert_kernel<<<dim3(D_ / 32, T_ / 32, B_), dim3(32, 8)>>>(x);
    row0_partial_kernel<<<dim3(D_ / 256, 8, B_), 256>>>(x);
    scores_mma_kernel<<<dim3(T_ / 128, T_ / 128, B_), 256, SMEM_BYTES>>>(att_w);
    softmax_kernel<<<dim3(T_, B_), 256>>>(att_w);
    av_mma_kernel<<<dim3(D_ / 128, T_ / 128, B_), 256, SMEM_BYTES>>>(att_vec);
    row0_final_kernel<<<dim3(D_ / 256, B_), 256>>>(att_vec);
}

// round 15
// speedup vs baseline: 1.3511x; 1.0033x over previous
#include <cuda_runtime.h>
#include <cuda_bf16.h>
#include <math.h>
#include <stdint.h>

// Attention_33492154974379:  x [B=8, T=2048, D=1024] fp32
// out = concat(att_vec [B,T,D], att_weights [B,T,T])
// R14: R12 base (bf16 hi/lo 3-term HMMA @ ~330TF/s ceiling, DIAG template,
//      prefix softmax float4, reversed-ti av, row-0 mean) +
//      float4/bf16x2 vectorized convert + __expf softmax.

#define B_ 8
#define T_ 2048
#define D_ 1024
#define NEG_INF_ (-1.0e9f)

// ---- static scratch ----
__device__ __nv_bfloat16 g_xhi[(size_t)B_ * T_ * D_];
__device__ __nv_bfloat16 g_xlo[(size_t)B_ * T_ * D_];
__device__ __nv_bfloat16 g_xthi[(size_t)B_ * D_ * T_];   // x^T [B,D,T]
__device__ __nv_bfloat16 g_xtlo[(size_t)B_ * D_ * T_];
__device__ __nv_bfloat16 g_whi[(size_t)B_ * T_ * T_];
__device__ __nv_bfloat16 g_wlo[(size_t)B_ * T_ * T_];
__device__ float g_r0[(size_t)B_ * 8 * D_];              // row-0 partial sums

// ---- smem: 4 tiles (Ahi,Alo,Bhi,Blo) of 128 x 32 bf16, stride 40 ----
#define LDS_ 40
#define TILE_E (128 * LDS_)
#define STAGE_E (4 * TILE_E)
#define SMEM_BYTES (2 * STAGE_E * 2)  // 81920 B double buffered

__device__ __forceinline__ void ldsm4(uint32_t* r, uint32_t a) {
    asm volatile("ldmatrix.sync.aligned.m8n8.x4.shared.b16 {%0,%1,%2,%3}, [%4];"
                 : "=r"(r[0]), "=r"(r[1]), "=r"(r[2]), "=r"(r[3]) : "r"(a));
}
__device__ __forceinline__ void mma16816(float* d, const uint32_t* a, const uint32_t* b) {
    asm volatile("mma.sync.aligned.m16n8k16.row.col.f32.bf16.bf16.f32 "
                 "{%0,%1,%2,%3}, {%4,%5,%6,%7}, {%8,%9}, {%0,%1,%2,%3};"
                 : "+f"(d[0]), "+f"(d[1]), "+f"(d[2]), "+f"(d[3])
                 : "r"(a[0]), "r"(a[1]), "r"(a[2]), "r"(a[3]), "r"(b[0]), "r"(b[1]));
}
__device__ __forceinline__ void cpa16(uint32_t d, const void* s) {
    asm volatile("cp.async.cg.shared.global [%0], [%1], 16;" :: "r"(d), "l"(s) : "memory");
}
__device__ __forceinline__ void cpcommit() { asm volatile("cp.async.commit_group;" ::: "memory"); }
template <int N>
__device__ __forceinline__ void cpwait() { asm volatile("cp.async.wait_group %0;" :: "n"(N) : "memory"); }

__device__ __forceinline__ void split_bf16(float v, __nv_bfloat16& hi, __nv_bfloat16& lo) {
    hi = __float2bfloat16_rn(v);
    lo = __float2bfloat16_rn(v - __bfloat162float(hi));
}

// ---------------------------------------------------------------------------
// Pass 0: x -> (hi,lo) and transposed (hi,lo). Tile 32(t) x 128(d), float4
// loads, bf16x2 stores both directions (smem transpose for the d-major side).
// ---------------------------------------------------------------------------
__global__ __launch_bounds__(256) void convert_kernel(const float* __restrict__ x) {
    __shared__ float tile[32][129];
    const int b = blockIdx.z;
    const int t0 = blockIdx.y * 32, d0 = blockIdx.x * 128;
    const int tid = threadIdx.x;
    const int tx = tid & 31;        // d: float4 index (32 x 4 = 128)
    const int ty = tid >> 5;        // t-row group (8)
    const float* xb = x + (size_t)b * T_ * D_;

    #pragma unroll
    for (int k = 0; k < 4; ++k) {
        const int tl = ty + k * 8;
        const float4 v = *(const float4*)(xb + (size_t)(t0 + tl) * D_ + d0 + tx * 4);
        tile[tl][tx * 4 + 0] = v.x; tile[tl][tx * 4 + 1] = v.y;
        tile[tl][tx * 4 + 2] = v.z; tile[tl][tx * 4 + 3] = v.w;
        __nv_bfloat16 h0, l0, h1, l1, h2, l2, h3, l3;
        split_bf16(v.x, h0, l0); split_bf16(v.y, h1, l1);
        split_bf16(v.z, h2, l2); split_bf16(v.w, h3, l3);
        const size_t o = (size_t)b * T_ * D_ + (size_t)(t0 + tl) * D_ + d0 + tx * 4;
        *(__nv_bfloat162*)(g_xhi + o)     = __nv_bfloat162(h0, h1);
        *(__nv_bfloat162*)(g_xhi + o + 2) = __nv_bfloat162(h2, h3);
        *(__nv_bfloat162*)(g_xlo + o)     = __nv_bfloat162(l0, l1);
        *(__nv_bfloat162*)(g_xlo + o + 2) = __nv_bfloat162(l2, l3);
    }
    __syncthreads();

    // transposed side: thread -> (d_local, t_pair)
    const int tp = (tid & 15) * 2;          // t pair 0..30
    #pragma unroll
    for (int k = 0; k < 8; ++k) {
        const int dl = (tid >> 4) + k * 16; // 0..127
        const float f0 = tile[tp][dl];
        const float f1 = tile[tp + 1][dl];
        __nv_bfloat16 h0, l0, h1, l1;
        split_bf16(f0, h0, l0); split_bf16(f1, h1, l1);
        const size_t o = (size_t)b * D_ * T_ + (size_t)(d0 + dl) * T_ + t0 + tp;
        *(__nv_bfloat162*)(g_xthi + o) = __nv_bfloat162(h0, h1);
        *(__nv_bfloat162*)(g_xtlo + o) = __nv_bfloat162(l0, l1);
    }
}

// ---------------------------------------------------------------------------
// Shared MMA mainloop (identical to R7/R12)
// ---------------------------------------------------------------------------
template <bool DIAG>
__device__ __forceinline__ void gemm_mainloop(
    const __nv_bfloat16* __restrict__ Ahi, const __nv_bfloat16* __restrict__ Alo,
    const __nv_bfloat16* __restrict__ Bhi, const __nv_bfloat16* __restrict__ Blo,
    int ldk, int kmax, float acc[4][4][4])
{
    extern __shared__ __nv_bfloat16 sm[];
    const int tid = threadIdx.x;
    const int lane = tid & 31, warp = tid >> 5;
    const int wm = (warp >> 2) * 64, wn = (warp & 3) * 32;
    const uint32_t smem_u32 = (uint32_t)__cvta_generic_to_shared(sm);

    const int tile = tid >> 6;
    const __nv_bfloat16* sp = (tile == 0) ? Ahi : (tile == 1) ? Alo : (tile == 2) ? Bhi : Blo;
    const int crow0 = (tid & 63) >> 2;
    const int cc = tid & 3;
    const uint32_t dtile = (uint32_t)(tile * TILE_E) * 2;

    const int nchunks = kmax >> 5;

    {
        #pragma unroll
        for (int t = 0; t < 8; ++t) {
            const int row = crow0 + t * 16;
            cpa16(smem_u32 + dtile + (uint32_t)(row * LDS_ + cc * 8) * 2,
                  sp + (size_t)row * ldk + cc * 8);
        }
        cpcommit();
    }

    for (int i = 0; i < nchunks; ++i) {
        const int s = i & 1;
        if (i + 1 < nchunks) {
            const int kk = (i + 1) << 5;
            const uint32_t dst0 = smem_u32 + (uint32_t)((s ^ 1) * STAGE_E) * 2 + dtile;
            #pragma unroll
            for (int t = 0; t < 8; ++t) {
                const int row = crow0 + t * 16;
                cpa16(dst0 + (uint32_t)(row * LDS_ + cc * 8) * 2,
                      sp + (size_t)row * ldk + kk + cc * 8);
            }
            cpcommit();
            cpwait<1>();
        } else {
            cpwait<0>();
        }
        __syncthreads();

        const uint32_t stA   = smem_u32 + (uint32_t)(s * STAGE_E) * 2;
        const uint32_t stAlo = stA + TILE_E * 2;
        const uint32_t stB   = stA + 2 * TILE_E * 2;
        const uint32_t stBlo = stA + 3 * TILE_E * 2;

        #pragma unroll
        for (int s2 = 0; s2 < 2; ++s2) {
            uint32_t ahi[4][4], alo[4][4], bhi[4][2], blo[4][2];
            const int ar = wm + (lane & 15);
            const int ac = ((lane >> 4) + 2 * s2) * 8;
            #pragma unroll
            for (int mt = 0; mt < 4; ++mt) {
                const uint32_t off = (uint32_t)((ar + mt * 16) * LDS_ + ac) * 2;
                ldsm4(ahi[mt], stA + off);
                ldsm4(alo[mt], stAlo + off);
            }
            const int br = wn + ((lane >> 4) & 1) * 8 + (lane & 7);
            const int bc = (((lane >> 3) & 1) + 2 * s2) * 8;
            #pragma unroll
            for (int p = 0; p < 2; ++p) {
                const uint32_t off = (uint32_t)((br + p * 16) * LDS_ + bc) * 2;
                uint32_t r4[4];
                ldsm4(r4, stB + off);
                bhi[2 * p][0] = r4[0]; bhi[2 * p][1] = r4[1];
                bhi[2 * p + 1][0] = r4[2]; bhi[2 * p + 1][1] = r4[3];
                ldsm4(r4, stBlo + off);
                blo[2 * p][0] = r4[0]; blo[2 * p][1] = r4[1];
                blo[2 * p + 1][0] = r4[2]; blo[2 * p + 1][1] = r4[3];
            }
            #pragma unroll
            for (int mt = 0; mt < 4; ++mt)
                #pragma unroll
                for (int nt = 0; nt < 4; ++nt) {
                    if (DIAG) {
                        if (wn + nt * 8 > wm + mt * 16 + 14) continue;
                    }
                    mma16816(acc[mt][nt], ahi[mt], bhi[nt]);
                    mma16816(acc[mt][nt], ahi[mt], blo[nt]);
                    mma16816(acc[mt][nt], alo[mt], bhi[nt]);
                }
        }
        __syncthreads();
    }
}

// ---------------------------------------------------------------------------
// Pass 1: masked scores. Upper tiles get final W=0.0f (softmax skips them).
// ---------------------------------------------------------------------------
__global__ __launch_bounds__(256, 2) void scores_mma_kernel(float* __restrict__ w) {
    const int b = blockIdx.z, ti = blockIdx.y, tj = blockIdx.x;
    float* wb = w + (size_t)b * T_ * T_;
    const int gi0 = ti * 128, gj0 = tj * 128;
    const int tid = threadIdx.x;

    if (tj > ti) {  // fully masked tile: write FINAL weight value 0.0f
        const float4 zv = make_float4(0.0f, 0.0f, 0.0f, 0.0f);
        #pragma unroll
        for (int t = 0; t < 16; ++t) {
            const int i = tid + t * 256;
            const int r = i >> 5, c4 = i & 31;
            *(float4*)(wb + (size_t)(gi0 + r) * T_ + gj0 + c4 * 4) = zv;
        }
        return;
    }

    float acc[4][4][4] = {};
    const size_t ao = ((size_t)b * T_ + gi0) * D_;
    const size_t bo = ((size_t)b * T_ + gj0) * D_;
    const bool diag = (ti == tj);
    if (diag)
        gemm_mainloop<true >(g_xhi + ao, g_xlo + ao, g_xhi + bo, g_xlo + bo, D_, D_, acc);
    else
        gemm_mainloop<false>(g_xhi + ao, g_xlo + ao, g_xhi + bo, g_xlo + bo, D_, D_, acc);

    const int lane = tid & 31, warp = tid >> 5;
    const int wm = (warp >> 2) * 64, wn = (warp & 3) * 32;
    #pragma unroll
    for (int mt = 0; mt < 4; ++mt)
        #pragma unroll
        for (int nt = 0; nt < 4; ++nt) {
            const int gi = gi0 + wm + mt * 16 + (lane >> 2);
            const int gj = gj0 + wn + nt * 8 + 2 * (lane & 3);
            float* p0 = wb + (size_t)gi * T_ + gj;
            float* p1 = wb + (size_t)(gi + 8) * T_ + gj;
            if (!diag) {
                p0[0] = acc[mt][nt][0]; p0[1] = acc[mt][nt][1];
                p1[0] = acc[mt][nt][2]; p1[1] = acc[mt][nt][3];
            } else {
                p0[0] = (gj     < gi    ) ? acc[mt][nt][0] : NEG_INF_;
                p0[1] = (gj + 1 < gi    ) ? acc[mt][nt][1] : NEG_INF_;
                p1[0] = (gj     < gi + 8) ? acc[mt][nt][2] : NEG_INF_;
                p1[1] = (gj + 1 < gi + 8) ? acc[mt][nt][3] : NEG_INF_;
            }
        }
}

// ---------------------------------------------------------------------------
// Pass 2: prefix softmax, float4/bf16x2 vectorized, __expf.
// Row i touches k < roundup(i+1,128). Row 0: uniform 1/T over the full row.
// ---------------------------------------------------------------------------
__global__ __launch_bounds__(256) void softmax_kernel(float* __restrict__ w) {
    const int b = blockIdx.y;
    const int i = blockIdx.x;
    const size_t row = (size_t)b * T_ + i;
    float* p = w + row * T_;
    __nv_bfloat162* ph2 = (__nv_bfloat162*)(g_whi + row * T_);
    __nv_bfloat162* pl2 = (__nv_bfloat162*)(g_wlo + row * T_);
    float4* p4 = (float4*)p;
    const int tid = threadIdx.x;

    if (i == 0) {
        const float val = 1.0f / (float)T_;
        const __nv_bfloat16 hb = __float2bfloat16_rn(val);
        const __nv_bfloat16 lb = __float2bfloat16_rn(val - __bfloat162float(hb));
        const float4 v4 = make_float4(val, val, val, val);
        const __nv_bfloat162 h2 = __nv_bfloat162(hb, hb);
        const __nv_bfloat162 l2 = __nv_bfloat162(lb, lb);
        #pragma unroll
        for (int j = 0; j < 2; ++j) {
            const int k4 = tid + j * 256;   // 512 float4 slots
            p4[k4] = v4;
            ph2[k4 * 2] = h2; ph2[k4 * 2 + 1] = h2;
            pl2[k4 * 2] = l2; pl2[k4 * 2 + 1] = l2;
        }
        return;
    }

    const int L4 = ((((i >> 7) + 1) << 7)) >> 2;   // 32..512 float4s

    float4 v[2];
    float m = -INFINITY;
    #pragma unroll
    for (int j = 0; j < 2; ++j) {
        const int k4 = tid + j * 256;
        v[j] = (k4 < L4) ? p4[k4] : make_float4(NEG_INF_, NEG_INF_, NEG_INF_, NEG_INF_);
        m = fmaxf(m, fmaxf(fmaxf(v[j].x, v[j].y), fmaxf(v[j].z, v[j].w)));
    }

    __shared__ float red[256];
    red[tid] = m; __syncthreads();
    #pragma unroll
    for (int s = 128; s > 0; s >>= 1) {
        if (tid < s) red[tid] = fmaxf(red[tid], red[tid + s]);
        __syncthreads();
    }
    m = red[0];
    __syncthreads();

    float sum = 0.0f;
    #pragma unroll
    for (int j = 0; j < 2; ++j) {
        v[j].x = __expf(v[j].x - m); v[j].y = __expf(v[j].y - m);
        v[j].z = __expf(v[j].z - m); v[j].w = __expf(v[j].w - m);
        sum += (v[j].x + v[j].y) + (v[j].z + v[j].w);
    }

    red[tid] = sum; __syncthreads();
    #pragma unroll
    for (int s = 128; s > 0; s >>= 1) {
        if (tid < s) red[tid] += red[tid + s];
        __syncthreads();
    }
    const float inv = 1.0f / red[0];

    #pragma unroll
    for (int j = 0; j < 2; ++j) {
        const int k4 = tid + j * 256;
        if (k4 < L4) {
            float4 o;
            o.x = v[j].x * inv; o.y = v[j].y * inv;
            o.z = v[j].z * inv; o.w = v[j].w * inv;
            p4[k4] = o;
            const __nv_bfloat16 h0 = __float2bfloat16_rn(o.x);
            const __nv_bfloat16 h1 = __float2bfloat16_rn(o.y);
            const __nv_bfloat16 h2v = __float2bfloat16_rn(o.z);
            const __nv_bfloat16 h3 = __float2bfloat16_rn(o.w);
            ph2[k4 * 2]     = __nv_bfloat162(h0, h1);
            ph2[k4 * 2 + 1] = __nv_bfloat162(h2v, h3);
            pl2[k4 * 2]     = __nv_bfloat162(
                __float2bfloat16_rn(o.x - __bfloat162float(h0)),
                __float2bfloat16_rn(o.y - __bfloat162float(h1)));
            pl2[k4 * 2 + 1] = __nv_bfloat162(
                __float2bfloat16_rn(o.z - __bfloat162float(h2v)),
                __float2bfloat16_rn(o.w - __bfloat162float(h3)));
        }
    }
}

// ---------------------------------------------------------------------------
// Pass 3: att_vec = W @ X, kmax=(ti+1)*128, long tiles first (reversed ti).
// ---------------------------------------------------------------------------
__global__ __launch_bounds__(256, 2) void av_mma_kernel(float* __restrict__ o) {
    const int b = blockIdx.z, tj = blockIdx.x;
    const int ti = (int)gridDim.y - 1 - (int)blockIdx.y;   // long tiles first
    const int gi0 = ti * 128, gj0 = tj * 128;
    const int kmax = (ti + 1) * 128;

    float acc[4][4][4] = {};
    const size_t ao = ((size_t)b * T_ + gi0) * T_;
    const size_t bo = ((size_t)b * D_ + gj0) * T_;
    gemm_mainloop<false>(g_whi + ao, g_wlo + ao, g_xthi + bo, g_xtlo + bo, T_, kmax, acc);

    float* ob = o + (size_t)b * T_ * D_;
    const int tid = threadIdx.x;
    const int lane = tid & 31, warp = tid >> 5;
    const int wm = (warp >> 2) * 64, wn = (warp & 3) * 32;
    #pragma unroll
    for (int mt = 0; mt < 4; ++mt)
        #pragma unroll
        for (int nt = 0; nt < 4; ++nt) {
            const int gi = gi0 + wm + mt * 16 + (lane >> 2);
            const int gj = gj0 + wn + nt * 8 + 2 * (lane & 3);
            float* p0 = ob + (size_t)gi * D_ + gj;
            float* p1 = ob + (size_t)(gi + 8) * D_ + gj;
            p0[0] = acc[mt][nt][0]; p0[1] = acc[mt][nt][1];
            p1[0] = acc[mt][nt][2]; p1[1] = acc[mt][nt][3];
        }
}

// ---------------------------------------------------------------------------
// Row-0 fix: av[b,0,:] = (1/T) * sum_s x[b,s,:]  (exact 2-stage reduction)
// ---------------------------------------------------------------------------
__global__ __launch_bounds__(256) void row0_partial_kernel(const float* __restrict__ x) {
    const int b = blockIdx.z, sp = blockIdx.y;       // 8 T-splits of 256 rows
    const int d = blockIdx.x * 256 + threadIdx.x;
    const float* xb = x + (size_t)b * T_ * D_ + (size_t)sp * 256 * D_ + d;
    float s = 0.0f;
    for (int r = 0; r < 256; ++r) s += xb[(size_t)r * D_];
    g_r0[((size_t)b * 8 + sp) * D_ + d] = s;
}
__global__ __launch_bounds__(256) void row0_final_kernel(float* __restrict__ o) {
    const int b = blockIdx.y;
    const int d = blockIdx.x * 256 + threadIdx.x;
    float s = 0.0f;
    #pragma unroll
    for (int j = 0; j < 8; ++j) s += g_r0[((size_t)b * 8 + j) * D_ + d];
    o[(size_t)b * T_ * D_ + d] = s * (1.0f / (float)T_);
}

// ---------------------------------------------------------------------------
extern "C" void kernel_launch(void* const* d_in, const int* in_sizes, int n_in,
                              void* d_out, int out_size) {
    const float* x = (const float*)d_in[0];
    float* att_vec = (float*)d_out;                          // [B,T,D]
    float* att_w   = (float*)d_out + (size_t)B_ * T_ * D_;   // [B,T,T]
    (void)in_sizes; (void)n_in; (void)out_size;

    cudaFuncSetAttribute(scores_mma_kernel, cudaFuncAttributeMaxDynamicSharedMemorySize, SMEM_BYTES);
    cudaFuncSetAttribute(av_mma_kernel, cudaFuncAttributeMaxDynamicSharedMemorySize, SMEM_BYTES);

    convert_kernel<<<dim3(D_ / 128, T_ / 32, B_), 256>>>(x);
    row0_partial_kernel<<<dim3(D_ / 256, 8, B_), 256>>>(x);
    scores_mma_kernel<<<dim3(T_ / 128, T_ / 128, B_), 256, SMEM_BYTES>>>(att_w);
    softmax_kernel<<<dim3(T_, B_), 256>>>(att_w);
    av_mma_kernel<<<dim3(D_ / 128, T_ / 128, B_), 256, SMEM_BYTES>>>(att_vec);
    row0_final_kernel<<<dim3(D_ / 256, B_), 256>>>(att_vec);
}